// round 11
// baseline (speedup 1.0000x reference)
#include <cuda_runtime.h>
#include <cuda_fp16.h>
#include <mma.h>
#include <cstdint>

using namespace nvcuda;

#define N_NODES_C 50000
#define N_PAIRS_C 800000
#define NHEADS_C 4
#define HEAD_DIM_C 64
#define NF_C 256   // NHEADS*HEAD_DIM
#define CAP 96
#define OVF_CAP 4096

// scratch (allocation-free rule: __device__ globals)
__device__ __half g_q[N_NODES_C * NF_C];
__device__ __half g_k[N_NODES_C * NF_C];
__device__ __half g_v[N_NODES_C * NF_C];
__device__ __half g_wh[3 * NHEADS_C * HEAD_DIM_C * HEAD_DIM_C]; // fp16 W
__device__ float  g_alpha[(size_t)N_PAIRS_C * NHEADS_C];

__device__ int   g_cnt[N_NODES_C];
__device__ int2  g_bkt[(size_t)N_NODES_C * CAP];
__device__ int   g_ovf_cnt;
__device__ int   g_ovf[OVF_CAP];

// ---------------------------------------------------------------------------
// Convert weights to fp16: g_wh[mat*16384 + h*4096 + e*64 + d]
// ---------------------------------------------------------------------------
__global__ void conv_w_kernel(const float* __restrict__ Wq,
                              const float* __restrict__ Wk,
                              const float* __restrict__ Wv) {
    int t = blockIdx.x * blockDim.x + threadIdx.x;
    int base = t * 4;
    if (base >= 3 * 16384) return;
    int mat = base >> 14;
    int r   = base & 16383;
    const float* src = (mat == 0) ? Wq : ((mat == 1) ? Wk : Wv);
    float4 f = *(const float4*)(src + r);
    __half2 h0 = __floats2half2_rn(f.x, f.y);
    __half2 h1 = __floats2half2_rn(f.z, f.w);
    uint2 out;
    out.x = *(const unsigned*)&h0;
    out.y = *(const unsigned*)&h1;
    *(uint2*)(g_wh + mat * 16384 + r) = out;
}

// ---------------------------------------------------------------------------
// Tensor-core projection v3: all operands via smem (LDSM).
// Block = 64 nodes x 1 matrix.  grid = (782, 3).  8 warps.
// smem: stage[8][256] f32 (8KB) | sW 4x64x64 fp16 (32KB) | sX[64][264] fp16 (33KB)
// Each warp handles 2 of the 16 (m-tile, head) items; 4-way et ILP inside.
// ---------------------------------------------------------------------------
#define PB_ROWS 64
#define SX_LD 264
#define PROJ_THREADS 256
#define SMEM_STAGE_F (8 * 256)                       // 2048 floats
#define SMEM_WMAT_H (NHEADS_C * 64 * 64)             // 16384 halfs
#define SMEM_X_H (PB_ROWS * SX_LD)                   // 16896 halfs
#define PROJ_SMEM_BYTES (SMEM_STAGE_F * 4 + (SMEM_WMAT_H + SMEM_X_H) * 2)

__global__ void __launch_bounds__(PROJ_THREADS)
proj_wmma_kernel(const float* __restrict__ x) {
    extern __shared__ float smraw[];
    float*  stage = smraw;                                // 2048 f32
    __half* sW = (__half*)(smraw + SMEM_STAGE_F);         // 16384 halfs
    __half* sX = sW + SMEM_WMAT_H;                        // 64*264 halfs

    const int tid  = threadIdx.x;
    const int warp = tid >> 5;
    const int lane = tid & 31;
    const int mat  = blockIdx.y;
    const int n0   = blockIdx.x * PB_ROWS;

    // stage this matrix's weights from L2-resident g_wh (2048 uint4)
    {
        const uint4* src = (const uint4*)(g_wh + mat * 16384);
        for (int i = tid; i < SMEM_WMAT_H / 8; i += PROJ_THREADS)
            ((uint4*)sW)[i] = src[i];
    }

    // load x tile coalesced fp32, convert to fp16 into padded smem
    for (int i = tid; i < PB_ROWS * 64; i += PROJ_THREADS) {
        int row = i >> 6, c4 = i & 63;
        int n = n0 + row;
        uint2 pack;
        if (n < N_NODES_C) {
            float4 f = __ldg((const float4*)(x + (size_t)n * NF_C + c4 * 4));
            __half2 h0 = __floats2half2_rn(f.x, f.y);
            __half2 h1 = __floats2half2_rn(f.z, f.w);
            pack.x = *(const unsigned*)&h0;
            pack.y = *(const unsigned*)&h1;
        } else {
            pack.x = 0u; pack.y = 0u;
        }
        *(uint2*)(sX + row * SX_LD + c4 * 4) = pack;
    }
    __syncthreads();

    __half* out = (mat == 0) ? g_q : ((mat == 1) ? g_k : g_v);
    float* st = stage + warp * 256;
    const int srow = lane >> 1;
    const int sseg = lane & 1;

#pragma unroll
    for (int it = 0; it < 2; it++) {
        int item = warp * 2 + it;          // 0..15
        int m = item >> 2;                 // m-tile 0..3
        int h = item & 3;                  // head 0..3

        // A fragments from smem (LDSM)
        wmma::fragment<wmma::matrix_a, 16, 16, 16, __half, wmma::row_major> a[4];
        const __half* Abase = sX + (m * 16) * SX_LD + h * HEAD_DIM_C;
#pragma unroll
        for (int kt = 0; kt < 4; kt++)
            wmma::load_matrix_sync(a[kt], Abase + kt * 16, SX_LD);

        const __half* Wb = sW + h * 4096;

        // 4 independent accumulator chains
        wmma::fragment<wmma::accumulator, 16, 16, 16, float> c[4];
#pragma unroll
        for (int et = 0; et < 4; et++)
            wmma::fill_fragment(c[et], 0.0f);

#pragma unroll
        for (int kt = 0; kt < 4; kt++) {
#pragma unroll
            for (int et = 0; et < 4; et++) {
                wmma::fragment<wmma::matrix_b, 16, 16, 16, __half, wmma::col_major> b;
                wmma::load_matrix_sync(b, Wb + et * 16 * 64 + kt * 16, 64);
                wmma::mma_sync(c[et], a[kt], b, c[et]);
            }
        }

        // staged writeback (fp32 -> fp16 pack, 16B stores)
        int row_g = n0 + m * 16 + srow;
        bool rok = (row_g < N_NODES_C);
#pragma unroll
        for (int et = 0; et < 4; et++) {
            wmma::store_matrix_sync(st, c[et], 16, wmma::mem_row_major);
            __syncwarp();
            if (rok) {
                const float* src = st + srow * 16 + sseg * 8;
                __half2 o0 = __floats2half2_rn(src[0], src[1]);
                __half2 o1 = __floats2half2_rn(src[2], src[3]);
                __half2 o2 = __floats2half2_rn(src[4], src[5]);
                __half2 o3 = __floats2half2_rn(src[6], src[7]);
                uint4 pack;
                pack.x = *(const unsigned*)&o0;
                pack.y = *(const unsigned*)&o1;
                pack.z = *(const unsigned*)&o2;
                pack.w = *(const unsigned*)&o3;
                *(uint4*)(out + (size_t)row_g * NF_C + h * HEAD_DIM_C
                          + et * 16 + sseg * 8) = pack;
            }
            __syncwarp();
        }
    }
}

// ---------------------------------------------------------------------------
// Bucket build
// ---------------------------------------------------------------------------
__global__ void zero_cnt_kernel() {
    int t = blockIdx.x * blockDim.x + threadIdx.x;
    if (t < N_NODES_C) g_cnt[t] = 0;
    if (t == 0) g_ovf_cnt = 0;
}

__global__ void bucket_kernel(const int* __restrict__ idx_i,
                              const int* __restrict__ idx_j) {
    int e = blockIdx.x * blockDim.x + threadIdx.x;
    if (e >= N_PAIRS_C) return;
    int i = idx_i[e];
    int pos = atomicAdd(&g_cnt[i], 1);
    if (pos < CAP) {
        g_bkt[(size_t)i * CAP + pos] = make_int2(e, idx_j[e]);
    } else {
        int p = atomicAdd(&g_ovf_cnt, 1);
        if (p < OVF_CAP) g_ovf[p] = e;
    }
}

// ---------------------------------------------------------------------------
// dot helper
// ---------------------------------------------------------------------------
__device__ __forceinline__ float dot8_h(uint4 qu, uint4 ku, float4 w0, float4 w1) {
    const __half2* q2 = (const __half2*)&qu;
    const __half2* k2 = (const __half2*)&ku;
    float2 qf0 = __half22float2(q2[0]);
    float2 qf1 = __half22float2(q2[1]);
    float2 qf2 = __half22float2(q2[2]);
    float2 qf3 = __half22float2(q2[3]);
    float2 kf0 = __half22float2(k2[0]);
    float2 kf1 = __half22float2(k2[1]);
    float2 kf2 = __half22float2(k2[2]);
    float2 kf3 = __half22float2(k2[3]);
    float s;
    s  = qf0.x * w0.x * kf0.x;
    s += qf0.y * w0.y * kf0.y;
    s += qf1.x * w0.z * kf1.x;
    s += qf1.y * w0.w * kf1.y;
    s += qf2.x * w1.x * kf2.x;
    s += qf2.y * w1.y * kf2.y;
    s += qf3.x * w1.z * kf3.x;
    s += qf3.y * w1.w * kf3.y;
    return s;
}

// ---------------------------------------------------------------------------
// Kernel A: alpha stream (2-edge unroll, measured-good version)
// ---------------------------------------------------------------------------
__global__ void __launch_bounds__(256)
alpha_kernel(const float* __restrict__ w_ij,
             const int* __restrict__ idx_i,
             const int* __restrict__ idx_j,
             const float* __restrict__ phi) {
    int warp = (blockIdx.x * blockDim.x + threadIdx.x) >> 5;
    int lane = threadIdx.x & 31;
    int e0 = warp * 2;
    if (e0 >= N_PAIRS_C) return;
    int e1 = e0 + 1;
    int off = lane * 8;

    int   i0 = __ldg(&idx_i[e0]), i1 = __ldg(&idx_i[e1]);
    int   j0 = __ldg(&idx_j[e0]), j1 = __ldg(&idx_j[e1]);
    float p0 = __ldg(&phi[e0]),   p1 = __ldg(&phi[e1]);

    const float4* wp0 = (const float4*)(w_ij + (size_t)e0 * NF_C + off);
    const float4* wp1 = (const float4*)(w_ij + (size_t)e1 * NF_C + off);
    float4 w00 = __ldcs(wp0);
    float4 w01 = __ldcs(wp0 + 1);
    float4 w10 = __ldcs(wp1);
    float4 w11 = __ldcs(wp1 + 1);

    uint4 qu0 = __ldg((const uint4*)(g_q + (size_t)i0 * NF_C + off));
    uint4 ku0 = __ldg((const uint4*)(g_k + (size_t)j0 * NF_C + off));
    uint4 qu1 = __ldg((const uint4*)(g_q + (size_t)i1 * NF_C + off));
    uint4 ku1 = __ldg((const uint4*)(g_k + (size_t)j1 * NF_C + off));

    float s0 = dot8_h(qu0, ku0, w00, w01);
    float s1 = dot8_h(qu1, ku1, w10, w11);

    s0 += __shfl_xor_sync(0xffffffffu, s0, 1);
    s1 += __shfl_xor_sync(0xffffffffu, s1, 1);
    s0 += __shfl_xor_sync(0xffffffffu, s0, 2);
    s1 += __shfl_xor_sync(0xffffffffu, s1, 2);
    s0 += __shfl_xor_sync(0xffffffffu, s0, 4);
    s1 += __shfl_xor_sync(0xffffffffu, s1, 4);

    if ((lane & 7) == 0) {
        int h = lane >> 3;
        g_alpha[(size_t)e0 * NHEADS_C + h] = s0 * 0.125f * p0;
        g_alpha[(size_t)e1 * NHEADS_C + h] = s1 * 0.125f * p1;
    }
}

// ---------------------------------------------------------------------------
// Kernel B: gather-accumulate (2-edge unroll, measured-good version)
// ---------------------------------------------------------------------------
__global__ void __launch_bounds__(256)
accum_kernel(float* __restrict__ y) {
    int node = (blockIdx.x * blockDim.x + threadIdx.x) >> 5;
    int lane = threadIdx.x & 31;
    if (node >= N_NODES_C) return;

    int deg = g_cnt[node];
    if (deg > CAP) deg = CAP;
    const size_t base = (size_t)node * CAP;
    const int off  = lane * 8;
    const int head = lane >> 3;

    float a0 = 0.f, a1 = 0.f, a2 = 0.f, a3 = 0.f;
    float a4 = 0.f, a5 = 0.f, a6 = 0.f, a7 = 0.f;

    int t = 0;
    for (; t + 2 <= deg; t += 2) {
        int2 m0 = g_bkt[base + t];
        int2 m1 = g_bkt[base + t + 1];
        float al0 = __ldg(&g_alpha[(size_t)m0.x * NHEADS_C + head]);
        float al1 = __ldg(&g_alpha[(size_t)m1.x * NHEADS_C + head]);
        uint4 vu0 = __ldg((const uint4*)(g_v + (size_t)m0.y * NF_C + off));
        uint4 vu1 = __ldg((const uint4*)(g_v + (size_t)m1.y * NF_C + off));

        const __half2* v20 = (const __half2*)&vu0;
        const __half2* v21 = (const __half2*)&vu1;
        float2 f;
        f = __half22float2(v20[0]); a0 = fmaf(al0, f.x, a0); a1 = fmaf(al0, f.y, a1);
        f = __half22float2(v20[1]); a2 = fmaf(al0, f.x, a2); a3 = fmaf(al0, f.y, a3);
        f = __half22float2(v20[2]); a4 = fmaf(al0, f.x, a4); a5 = fmaf(al0, f.y, a5);
        f = __half22float2(v20[3]); a6 = fmaf(al0, f.x, a6); a7 = fmaf(al0, f.y, a7);
        f = __half22float2(v21[0]); a0 = fmaf(al1, f.x, a0); a1 = fmaf(al1, f.y, a1);
        f = __half22float2(v21[1]); a2 = fmaf(al1, f.x, a2); a3 = fmaf(al1, f.y, a3);
        f = __half22float2(v21[2]); a4 = fmaf(al1, f.x, a4); a5 = fmaf(al1, f.y, a5);
        f = __half22float2(v21[3]); a6 = fmaf(al1, f.x, a6); a7 = fmaf(al1, f.y, a7);
    }
    if (t < deg) {
        int2 m0 = g_bkt[base + t];
        float al0 = __ldg(&g_alpha[(size_t)m0.x * NHEADS_C + head]);
        uint4 vu0 = __ldg((const uint4*)(g_v + (size_t)m0.y * NF_C + off));
        const __half2* v20 = (const __half2*)&vu0;
        float2 f;
        f = __half22float2(v20[0]); a0 = fmaf(al0, f.x, a0); a1 = fmaf(al0, f.y, a1);
        f = __half22float2(v20[1]); a2 = fmaf(al0, f.x, a2); a3 = fmaf(al0, f.y, a3);
        f = __half22float2(v20[2]); a4 = fmaf(al0, f.x, a4); a5 = fmaf(al0, f.y, a5);
        f = __half22float2(v20[3]); a6 = fmaf(al0, f.x, a6); a7 = fmaf(al0, f.y, a7);
    }

    float4* yp = (float4*)(y + (size_t)node * NF_C + off);
    yp[0] = make_float4(a0, a1, a2, a3);
    yp[1] = make_float4(a4, a5, a6, a7);
}

// ---------------------------------------------------------------------------
// Overflow fallback
// ---------------------------------------------------------------------------
__global__ void overflow_kernel(const int* __restrict__ idx_i,
                                const int* __restrict__ idx_j,
                                float* __restrict__ y) {
    int n = g_ovf_cnt;
    if (n > OVF_CAP) n = OVF_CAP;
    int lane = threadIdx.x & 31;
    for (int t = (int)(threadIdx.x >> 5); t < n; t += (int)(blockDim.x >> 5)) {
        int e = g_ovf[t];
        int i = idx_i[e];
        int j = idx_j[e];
        int off = lane * 8;
        int head = lane >> 3;

        float alpha = g_alpha[(size_t)e * NHEADS_C + head];
        uint4 vu = *(const uint4*)(g_v + (size_t)j * NF_C + off);
        const __half2* v2 = (const __half2*)&vu;
        float2 f0 = __half22float2(v2[0]);
        float2 f1 = __half22float2(v2[1]);
        float2 f2 = __half22float2(v2[2]);
        float2 f3 = __half22float2(v2[3]);
        float* yp = y + (size_t)i * NF_C + off;
        atomicAdd(yp + 0, alpha * f0.x);
        atomicAdd(yp + 1, alpha * f0.y);
        atomicAdd(yp + 2, alpha * f1.x);
        atomicAdd(yp + 3, alpha * f1.y);
        atomicAdd(yp + 4, alpha * f2.x);
        atomicAdd(yp + 5, alpha * f2.y);
        atomicAdd(yp + 6, alpha * f3.x);
        atomicAdd(yp + 7, alpha * f3.y);
    }
}

// ---------------------------------------------------------------------------
// launch
// ---------------------------------------------------------------------------
extern "C" void kernel_launch(void* const* d_in, const int* in_sizes, int n_in,
                              void* d_out, int out_size) {
    const float* x     = (const float*)d_in[0];
    const float* w_ij  = (const float*)d_in[1];
    const int*   idx_i = (const int*)d_in[2];
    const int*   idx_j = (const int*)d_in[3];
    const float* phi   = (const float*)d_in[4];
    const float* Wq    = (const float*)d_in[5];
    const float* Wk    = (const float*)d_in[6];
    const float* Wv    = (const float*)d_in[7];
    float* y = (float*)d_out;

    // fp16 weight conversion
    conv_w_kernel<<<48, 256>>>(Wq, Wk, Wv);

    // bucket build
    zero_cnt_kernel<<<(N_NODES_C + 255) / 256, 256>>>();
    bucket_kernel<<<(N_PAIRS_C + 255) / 256, 256>>>(idx_i, idx_j);

    // tensor-core projection (all operands via smem / LDSM)
    cudaFuncSetAttribute(proj_wmma_kernel,
                         cudaFuncAttributeMaxDynamicSharedMemorySize,
                         PROJ_SMEM_BYTES);
    dim3 pgrid((N_NODES_C + PB_ROWS - 1) / PB_ROWS, 3);   // (782, 3)
    proj_wmma_kernel<<<pgrid, PROJ_THREADS, PROJ_SMEM_BYTES>>>(x);

    // A: alpha stream (2 edges per warp)
    int ablocks = (N_PAIRS_C + 15) / 16;
    alpha_kernel<<<ablocks, 256>>>(w_ij, idx_i, idx_j, phi);

    // B: gather-accumulate
    int nblocks = (N_NODES_C + 7) / 8;
    accum_kernel<<<nblocks, 256>>>(y);

    // overflow (usually empty)
    overflow_kernel<<<1, 256>>>(idx_i, idx_j, y);
}

// round 13
// speedup vs baseline: 1.2151x; 1.2151x over previous
#include <cuda_runtime.h>
#include <cuda_fp16.h>
#include <mma.h>
#include <cstdint>

using namespace nvcuda;

#define N_NODES_C 50000
#define N_PAIRS_C 800000
#define NHEADS_C 4
#define HEAD_DIM_C 64
#define NF_C 256   // NHEADS*HEAD_DIM
#define CAP 96
#define OVF_CAP 4096

// scratch (allocation-free rule: __device__ globals)
__device__ __half g_q[N_NODES_C * NF_C];
__device__ __half g_k[N_NODES_C * NF_C];
__device__ __half g_v[N_NODES_C * NF_C];
__device__ __half g_wh[3 * NHEADS_C * HEAD_DIM_C * HEAD_DIM_C]; // fp16 W
__device__ float  g_alpha[(size_t)N_PAIRS_C * NHEADS_C];

__device__ int   g_cnt[N_NODES_C];
__device__ int2  g_bkt[(size_t)N_NODES_C * CAP];
__device__ int   g_ovf_cnt;
__device__ int   g_ovf[OVF_CAP];

// ---------------------------------------------------------------------------
// Convert weights to fp16: g_wh[mat*16384 + h*4096 + e*64 + d]
// ---------------------------------------------------------------------------
__global__ void conv_w_kernel(const float* __restrict__ Wq,
                              const float* __restrict__ Wk,
                              const float* __restrict__ Wv) {
    int t = blockIdx.x * blockDim.x + threadIdx.x;
    int base = t * 4;
    if (base >= 3 * 16384) return;
    int mat = base >> 14;
    int r   = base & 16383;
    const float* src = (mat == 0) ? Wq : ((mat == 1) ? Wk : Wv);
    float4 f = *(const float4*)(src + r);
    __half2 h0 = __floats2half2_rn(f.x, f.y);
    __half2 h1 = __floats2half2_rn(f.z, f.w);
    uint2 out;
    out.x = *(const unsigned*)&h0;
    out.y = *(const unsigned*)&h1;
    *(uint2*)(g_wh + mat * 16384 + r) = out;
}

// ---------------------------------------------------------------------------
// Tensor-core projection v4 (fixed):
//  - W in smem with pitch 72 halfs (144B rows -> conflict-free LDSM)
//  - x tile in smem pitch 264 (conflict-free), converted fp32->fp16 on load
//  - fp32 accum -> fp16 fragment -> store_matrix_sync DIRECTLY to global
// Block = 64 nodes x 1 matrix.  grid = (782, 3).  8 warps, 2 items each.
// ---------------------------------------------------------------------------
#define PB_ROWS 64
#define SX_LD 264
#define SW_LD 72                       // padded pitch for W columns
#define PROJ_THREADS 256
#define SMEM_WMAT_H (NHEADS_C * 64 * SW_LD)          // 18432 halfs (36KB)
#define SMEM_X_H (PB_ROWS * SX_LD)                   // 16896 halfs (33KB)
#define PROJ_SMEM_BYTES ((SMEM_WMAT_H + SMEM_X_H) * 2)

__global__ void __launch_bounds__(PROJ_THREADS)
proj_wmma_kernel(const float* __restrict__ x) {
    extern __shared__ __half smh[];
    __half* sW = smh;                 // [ (h*64+e)*72 + d ]
    __half* sX = smh + SMEM_WMAT_H;   // [ row*264 + col ]

    const int tid  = threadIdx.x;
    const int warp = tid >> 5;
    const int mat  = blockIdx.y;
    const int n0   = blockIdx.x * PB_ROWS;

    // stage this matrix's weights with padded pitch.
    // 256 rows x 64 halfs; each row = 8 x uint4 (8 halfs per uint4).
    {
        const __half* src = g_wh + mat * 16384;
        for (int i = tid; i < NHEADS_C * 64 * 8; i += PROJ_THREADS) {
            int row = i >> 3;          // (h*64+e), 0..255
            int seg = i & 7;           // 8 halfs per uint4 segment
            uint4 v = *(const uint4*)(src + row * 64 + seg * 8);
            *(uint4*)(sW + row * SW_LD + seg * 8) = v;   // 144B row pitch, 16B aligned
        }
    }

    // load x tile coalesced fp32, convert to fp16 into padded smem
    for (int i = tid; i < PB_ROWS * 64; i += PROJ_THREADS) {
        int row = i >> 6, c4 = i & 63;
        int n = n0 + row;
        uint2 pack;
        if (n < N_NODES_C) {
            float4 f = __ldg((const float4*)(x + (size_t)n * NF_C + c4 * 4));
            __half2 h0 = __floats2half2_rn(f.x, f.y);
            __half2 h1 = __floats2half2_rn(f.z, f.w);
            pack.x = *(const unsigned*)&h0;
            pack.y = *(const unsigned*)&h1;
        } else {
            pack.x = 0u; pack.y = 0u;
        }
        *(uint2*)(sX + row * SX_LD + c4 * 4) = pack;
    }
    __syncthreads();

    __half* out = (mat == 0) ? g_q : ((mat == 1) ? g_k : g_v);

#pragma unroll
    for (int it = 0; it < 2; it++) {
        int item = warp * 2 + it;          // 0..15
        int m = item >> 2;                 // m-tile 0..3
        int h = item & 3;                  // head 0..3
        int row0 = n0 + m * 16;
        if (row0 >= N_NODES_C) continue;   // tiles fully valid or invalid (50000%16==0)

        // A fragments from smem (LDSM, stride 264: conflict-free)
        wmma::fragment<wmma::matrix_a, 16, 16, 16, __half, wmma::row_major> a[4];
        const __half* Abase = sX + (m * 16) * SX_LD + h * HEAD_DIM_C;
#pragma unroll
        for (int kt = 0; kt < 4; kt++)
            wmma::load_matrix_sync(a[kt], Abase + kt * 16, SX_LD);

        const __half* Wb = sW + h * 64 * SW_LD;

        // 4 independent accumulator chains
        wmma::fragment<wmma::accumulator, 16, 16, 16, float> c[4];
#pragma unroll
        for (int et = 0; et < 4; et++)
            wmma::fill_fragment(c[et], 0.0f);

#pragma unroll
        for (int kt = 0; kt < 4; kt++) {
#pragma unroll
            for (int et = 0; et < 4; et++) {
                wmma::fragment<wmma::matrix_b, 16, 16, 16, __half, wmma::col_major> b;
                wmma::load_matrix_sync(b, Wb + et * 16 * SW_LD + kt * 16, SW_LD);
                wmma::mma_sync(c[et], a[kt], b, c[et]);
            }
        }

        // fp32 -> fp16 fragment conversion, direct global store (no staging)
#pragma unroll
        for (int et = 0; et < 4; et++) {
            wmma::fragment<wmma::accumulator, 16, 16, 16, __half> ch;
#pragma unroll
            for (int i = 0; i < ch.num_elements; i++)
                ch.x[i] = __float2half_rn(c[et].x[i]);
            wmma::store_matrix_sync(out + (size_t)row0 * NF_C + h * HEAD_DIM_C + et * 16,
                                    ch, NF_C, wmma::mem_row_major);
        }
    }
}

// ---------------------------------------------------------------------------
// Bucket build
// ---------------------------------------------------------------------------
__global__ void zero_cnt_kernel() {
    int t = blockIdx.x * blockDim.x + threadIdx.x;
    if (t < N_NODES_C) g_cnt[t] = 0;
    if (t == 0) g_ovf_cnt = 0;
}

__global__ void bucket_kernel(const int* __restrict__ idx_i,
                              const int* __restrict__ idx_j) {
    int e = blockIdx.x * blockDim.x + threadIdx.x;
    if (e >= N_PAIRS_C) return;
    int i = idx_i[e];
    int pos = atomicAdd(&g_cnt[i], 1);
    if (pos < CAP) {
        g_bkt[(size_t)i * CAP + pos] = make_int2(e, idx_j[e]);
    } else {
        int p = atomicAdd(&g_ovf_cnt, 1);
        if (p < OVF_CAP) g_ovf[p] = e;
    }
}

// ---------------------------------------------------------------------------
// dot helper
// ---------------------------------------------------------------------------
__device__ __forceinline__ float dot8_h(uint4 qu, uint4 ku, float4 w0, float4 w1) {
    const __half2* q2 = (const __half2*)&qu;
    const __half2* k2 = (const __half2*)&ku;
    float2 qf0 = __half22float2(q2[0]);
    float2 qf1 = __half22float2(q2[1]);
    float2 qf2 = __half22float2(q2[2]);
    float2 qf3 = __half22float2(q2[3]);
    float2 kf0 = __half22float2(k2[0]);
    float2 kf1 = __half22float2(k2[1]);
    float2 kf2 = __half22float2(k2[2]);
    float2 kf3 = __half22float2(k2[3]);
    float s;
    s  = qf0.x * w0.x * kf0.x;
    s += qf0.y * w0.y * kf0.y;
    s += qf1.x * w0.z * kf1.x;
    s += qf1.y * w0.w * kf1.y;
    s += qf2.x * w1.x * kf2.x;
    s += qf2.y * w1.y * kf2.y;
    s += qf3.x * w1.z * kf3.x;
    s += qf3.y * w1.w * kf3.y;
    return s;
}

// ---------------------------------------------------------------------------
// Kernel A: alpha stream (2-edge unroll, measured-good version)
// ---------------------------------------------------------------------------
__global__ void __launch_bounds__(256)
alpha_kernel(const float* __restrict__ w_ij,
             const int* __restrict__ idx_i,
             const int* __restrict__ idx_j,
             const float* __restrict__ phi) {
    int warp = (blockIdx.x * blockDim.x + threadIdx.x) >> 5;
    int lane = threadIdx.x & 31;
    int e0 = warp * 2;
    if (e0 >= N_PAIRS_C) return;
    int e1 = e0 + 1;
    int off = lane * 8;

    int   i0 = __ldg(&idx_i[e0]), i1 = __ldg(&idx_i[e1]);
    int   j0 = __ldg(&idx_j[e0]), j1 = __ldg(&idx_j[e1]);
    float p0 = __ldg(&phi[e0]),   p1 = __ldg(&phi[e1]);

    const float4* wp0 = (const float4*)(w_ij + (size_t)e0 * NF_C + off);
    const float4* wp1 = (const float4*)(w_ij + (size_t)e1 * NF_C + off);
    float4 w00 = __ldcs(wp0);
    float4 w01 = __ldcs(wp0 + 1);
    float4 w10 = __ldcs(wp1);
    float4 w11 = __ldcs(wp1 + 1);

    uint4 qu0 = __ldg((const uint4*)(g_q + (size_t)i0 * NF_C + off));
    uint4 ku0 = __ldg((const uint4*)(g_k + (size_t)j0 * NF_C + off));
    uint4 qu1 = __ldg((const uint4*)(g_q + (size_t)i1 * NF_C + off));
    uint4 ku1 = __ldg((const uint4*)(g_k + (size_t)j1 * NF_C + off));

    float s0 = dot8_h(qu0, ku0, w00, w01);
    float s1 = dot8_h(qu1, ku1, w10, w11);

    s0 += __shfl_xor_sync(0xffffffffu, s0, 1);
    s1 += __shfl_xor_sync(0xffffffffu, s1, 1);
    s0 += __shfl_xor_sync(0xffffffffu, s0, 2);
    s1 += __shfl_xor_sync(0xffffffffu, s1, 2);
    s0 += __shfl_xor_sync(0xffffffffu, s0, 4);
    s1 += __shfl_xor_sync(0xffffffffu, s1, 4);

    if ((lane & 7) == 0) {
        int h = lane >> 3;
        g_alpha[(size_t)e0 * NHEADS_C + h] = s0 * 0.125f * p0;
        g_alpha[(size_t)e1 * NHEADS_C + h] = s1 * 0.125f * p1;
    }
}

// ---------------------------------------------------------------------------
// Kernel B: gather-accumulate (2-edge unroll, measured-good version)
// ---------------------------------------------------------------------------
__global__ void __launch_bounds__(256)
accum_kernel(float* __restrict__ y) {
    int node = (blockIdx.x * blockDim.x + threadIdx.x) >> 5;
    int lane = threadIdx.x & 31;
    if (node >= N_NODES_C) return;

    int deg = g_cnt[node];
    if (deg > CAP) deg = CAP;
    const size_t base = (size_t)node * CAP;
    const int off  = lane * 8;
    const int head = lane >> 3;

    float a0 = 0.f, a1 = 0.f, a2 = 0.f, a3 = 0.f;
    float a4 = 0.f, a5 = 0.f, a6 = 0.f, a7 = 0.f;

    int t = 0;
    for (; t + 2 <= deg; t += 2) {
        int2 m0 = g_bkt[base + t];
        int2 m1 = g_bkt[base + t + 1];
        float al0 = __ldg(&g_alpha[(size_t)m0.x * NHEADS_C + head]);
        float al1 = __ldg(&g_alpha[(size_t)m1.x * NHEADS_C + head]);
        uint4 vu0 = __ldg((const uint4*)(g_v + (size_t)m0.y * NF_C + off));
        uint4 vu1 = __ldg((const uint4*)(g_v + (size_t)m1.y * NF_C + off));

        const __half2* v20 = (const __half2*)&vu0;
        const __half2* v21 = (const __half2*)&vu1;
        float2 f;
        f = __half22float2(v20[0]); a0 = fmaf(al0, f.x, a0); a1 = fmaf(al0, f.y, a1);
        f = __half22float2(v20[1]); a2 = fmaf(al0, f.x, a2); a3 = fmaf(al0, f.y, a3);
        f = __half22float2(v20[2]); a4 = fmaf(al0, f.x, a4); a5 = fmaf(al0, f.y, a5);
        f = __half22float2(v20[3]); a6 = fmaf(al0, f.x, a6); a7 = fmaf(al0, f.y, a7);
        f = __half22float2(v21[0]); a0 = fmaf(al1, f.x, a0); a1 = fmaf(al1, f.y, a1);
        f = __half22float2(v21[1]); a2 = fmaf(al1, f.x, a2); a3 = fmaf(al1, f.y, a3);
        f = __half22float2(v21[2]); a4 = fmaf(al1, f.x, a4); a5 = fmaf(al1, f.y, a5);
        f = __half22float2(v21[3]); a6 = fmaf(al1, f.x, a6); a7 = fmaf(al1, f.y, a7);
    }
    if (t < deg) {
        int2 m0 = g_bkt[base + t];
        float al0 = __ldg(&g_alpha[(size_t)m0.x * NHEADS_C + head]);
        uint4 vu0 = __ldg((const uint4*)(g_v + (size_t)m0.y * NF_C + off));
        const __half2* v20 = (const __half2*)&vu0;
        float2 f;
        f = __half22float2(v20[0]); a0 = fmaf(al0, f.x, a0); a1 = fmaf(al0, f.y, a1);
        f = __half22float2(v20[1]); a2 = fmaf(al0, f.x, a2); a3 = fmaf(al0, f.y, a3);
        f = __half22float2(v20[2]); a4 = fmaf(al0, f.x, a4); a5 = fmaf(al0, f.y, a5);
        f = __half22float2(v20[3]); a6 = fmaf(al0, f.x, a6); a7 = fmaf(al0, f.y, a7);
    }

    float4* yp = (float4*)(y + (size_t)node * NF_C + off);
    yp[0] = make_float4(a0, a1, a2, a3);
    yp[1] = make_float4(a4, a5, a6, a7);
}

// ---------------------------------------------------------------------------
// Overflow fallback
// ---------------------------------------------------------------------------
__global__ void overflow_kernel(const int* __restrict__ idx_i,
                                const int* __restrict__ idx_j,
                                float* __restrict__ y) {
    int n = g_ovf_cnt;
    if (n > OVF_CAP) n = OVF_CAP;
    int lane = threadIdx.x & 31;
    for (int t = (int)(threadIdx.x >> 5); t < n; t += (int)(blockDim.x >> 5)) {
        int e = g_ovf[t];
        int i = idx_i[e];
        int j = idx_j[e];
        int off = lane * 8;
        int head = lane >> 3;

        float alpha = g_alpha[(size_t)e * NHEADS_C + head];
        uint4 vu = *(const uint4*)(g_v + (size_t)j * NF_C + off);
        const __half2* v2 = (const __half2*)&vu;
        float2 f0 = __half22float2(v2[0]);
        float2 f1 = __half22float2(v2[1]);
        float2 f2 = __half22float2(v2[2]);
        float2 f3 = __half22float2(v2[3]);
        float* yp = y + (size_t)i * NF_C + off;
        atomicAdd(yp + 0, alpha * f0.x);
        atomicAdd(yp + 1, alpha * f0.y);
        atomicAdd(yp + 2, alpha * f1.x);
        atomicAdd(yp + 3, alpha * f1.y);
        atomicAdd(yp + 4, alpha * f2.x);
        atomicAdd(yp + 5, alpha * f2.y);
        atomicAdd(yp + 6, alpha * f3.x);
        atomicAdd(yp + 7, alpha * f3.y);
    }
}

// ---------------------------------------------------------------------------
// launch
// ---------------------------------------------------------------------------
extern "C" void kernel_launch(void* const* d_in, const int* in_sizes, int n_in,
                              void* d_out, int out_size) {
    const float* x     = (const float*)d_in[0];
    const float* w_ij  = (const float*)d_in[1];
    const int*   idx_i = (const int*)d_in[2];
    const int*   idx_j = (const int*)d_in[3];
    const float* phi   = (const float*)d_in[4];
    const float* Wq    = (const float*)d_in[5];
    const float* Wk    = (const float*)d_in[6];
    const float* Wv    = (const float*)d_in[7];
    float* y = (float*)d_out;

    // fp16 weight conversion
    conv_w_kernel<<<48, 256>>>(Wq, Wk, Wv);

    // bucket build
    zero_cnt_kernel<<<(N_NODES_C + 255) / 256, 256>>>();
    bucket_kernel<<<(N_PAIRS_C + 255) / 256, 256>>>(idx_i, idx_j);

    // tensor-core projection (conflict-free LDSM, direct fp16 store)
    cudaFuncSetAttribute(proj_wmma_kernel,
                         cudaFuncAttributeMaxDynamicSharedMemorySize,
                         PROJ_SMEM_BYTES);
    dim3 pgrid((N_NODES_C + PB_ROWS - 1) / PB_ROWS, 3);   // (782, 3)
    proj_wmma_kernel<<<pgrid, PROJ_THREADS, PROJ_SMEM_BYTES>>>(x);

    // A: alpha stream (2 edges per warp)
    int ablocks = (N_PAIRS_C + 15) / 16;
    alpha_kernel<<<ablocks, 256>>>(w_ij, idx_i, idx_j, phi);

    // B: gather-accumulate
    int nblocks = (N_NODES_C + 7) / 8;
    accum_kernel<<<nblocks, 256>>>(y);

    // overflow (usually empty)
    overflow_kernel<<<1, 256>>>(idx_i, idx_j, y);
}

// round 14
// speedup vs baseline: 1.2516x; 1.0300x over previous
#include <cuda_runtime.h>
#include <cuda_fp16.h>
#include <mma.h>
#include <cstdint>

using namespace nvcuda;

#define N_NODES_C 50000
#define N_PAIRS_C 800000
#define NHEADS_C 4
#define HEAD_DIM_C 64
#define NF_C 256   // NHEADS*HEAD_DIM
#define CAP 96
#define OVF_CAP 4096

// scratch (allocation-free rule: __device__ globals)
__device__ __half g_q[N_NODES_C * NF_C];
__device__ __half g_k[N_NODES_C * NF_C];
__device__ __half g_v[N_NODES_C * NF_C];
__device__ __half g_wh[3 * NHEADS_C * HEAD_DIM_C * HEAD_DIM_C]; // fp16 W
__device__ float  g_alpha[(size_t)N_PAIRS_C * NHEADS_C];

__device__ int   g_cnt[N_NODES_C];
__device__ int2  g_bkt[(size_t)N_NODES_C * CAP];
__device__ int   g_ovf_cnt;
__device__ int   g_ovf[OVF_CAP];

// ---------------------------------------------------------------------------
// Convert weights to fp16: g_wh[mat*16384 + h*4096 + e*64 + d]
// ---------------------------------------------------------------------------
__global__ void conv_w_kernel(const float* __restrict__ Wq,
                              const float* __restrict__ Wk,
                              const float* __restrict__ Wv) {
    int t = blockIdx.x * blockDim.x + threadIdx.x;
    int base = t * 4;
    if (base >= 3 * 16384) return;
    int mat = base >> 14;
    int r   = base & 16383;
    const float* src = (mat == 0) ? Wq : ((mat == 1) ? Wk : Wv);
    float4 f = *(const float4*)(src + r);
    __half2 h0 = __floats2half2_rn(f.x, f.y);
    __half2 h1 = __floats2half2_rn(f.z, f.w);
    uint2 out;
    out.x = *(const unsigned*)&h0;
    out.y = *(const unsigned*)&h1;
    *(uint2*)(g_wh + mat * 16384 + r) = out;
}

// ---------------------------------------------------------------------------
// Tensor-core projection v5:
//  - 512 threads / 128 rows per block -> 102KB smem, 2 blocks/SM, 32 warps/SM
//  - W in smem pitch 72 (conflict-free LDSM), x pitch 264 (conflict-free)
//  - fp32 accum -> fp16 fragment -> direct global store_matrix_sync
// grid = (391, 3).  16 warps, 2 items each (32 items = 8 m-tiles x 4 heads).
// ---------------------------------------------------------------------------
#define PB_ROWS 128
#define SX_LD 264
#define SW_LD 72
#define PROJ_THREADS 512
#define SMEM_WMAT_H (NHEADS_C * 64 * SW_LD)          // 18432 halfs (36KB)
#define SMEM_X_H (PB_ROWS * SX_LD)                   // 33792 halfs (66KB)
#define PROJ_SMEM_BYTES ((SMEM_WMAT_H + SMEM_X_H) * 2)

__global__ void __launch_bounds__(PROJ_THREADS)
proj_wmma_kernel(const float* __restrict__ x) {
    extern __shared__ __half smh[];
    __half* sW = smh;                 // [ (h*64+e)*72 + d ]
    __half* sX = smh + SMEM_WMAT_H;   // [ row*264 + col ]

    const int tid  = threadIdx.x;
    const int warp = tid >> 5;
    const int mat  = blockIdx.y;
    const int n0   = blockIdx.x * PB_ROWS;

    // stage weights with padded pitch: 256 rows x 64 halfs, 8 x uint4 per row
    {
        const __half* src = g_wh + mat * 16384;
        for (int i = tid; i < NHEADS_C * 64 * 8; i += PROJ_THREADS) {
            int row = i >> 3;
            int seg = i & 7;
            uint4 v = *(const uint4*)(src + row * 64 + seg * 8);
            *(uint4*)(sW + row * SW_LD + seg * 8) = v;
        }
    }

    // load x tile coalesced fp32, convert to fp16 into padded smem
    for (int i = tid; i < PB_ROWS * 64; i += PROJ_THREADS) {
        int row = i >> 6, c4 = i & 63;
        int n = n0 + row;
        uint2 pack;
        if (n < N_NODES_C) {
            float4 f = __ldg((const float4*)(x + (size_t)n * NF_C + c4 * 4));
            __half2 h0 = __floats2half2_rn(f.x, f.y);
            __half2 h1 = __floats2half2_rn(f.z, f.w);
            pack.x = *(const unsigned*)&h0;
            pack.y = *(const unsigned*)&h1;
        } else {
            pack.x = 0u; pack.y = 0u;
        }
        *(uint2*)(sX + row * SX_LD + c4 * 4) = pack;
    }
    __syncthreads();

    __half* out = (mat == 0) ? g_q : ((mat == 1) ? g_k : g_v);

#pragma unroll
    for (int it = 0; it < 2; it++) {
        int item = warp * 2 + it;          // 0..31
        int m = item >> 2;                 // m-tile 0..7
        int h = item & 3;                  // head 0..3
        int row0 = n0 + m * 16;
        if (row0 >= N_NODES_C) continue;   // tiles fully valid or invalid (50000%16==0)

        // A fragments from smem (LDSM, stride 264: conflict-free)
        wmma::fragment<wmma::matrix_a, 16, 16, 16, __half, wmma::row_major> a[4];
        const __half* Abase = sX + (m * 16) * SX_LD + h * HEAD_DIM_C;
#pragma unroll
        for (int kt = 0; kt < 4; kt++)
            wmma::load_matrix_sync(a[kt], Abase + kt * 16, SX_LD);

        const __half* Wb = sW + h * 64 * SW_LD;

        // 4 independent accumulator chains
        wmma::fragment<wmma::accumulator, 16, 16, 16, float> c[4];
#pragma unroll
        for (int et = 0; et < 4; et++)
            wmma::fill_fragment(c[et], 0.0f);

#pragma unroll
        for (int kt = 0; kt < 4; kt++) {
#pragma unroll
            for (int et = 0; et < 4; et++) {
                wmma::fragment<wmma::matrix_b, 16, 16, 16, __half, wmma::col_major> b;
                wmma::load_matrix_sync(b, Wb + et * 16 * SW_LD + kt * 16, SW_LD);
                wmma::mma_sync(c[et], a[kt], b, c[et]);
            }
        }

        // fp32 -> fp16 fragment conversion, direct global store
#pragma unroll
        for (int et = 0; et < 4; et++) {
            wmma::fragment<wmma::accumulator, 16, 16, 16, __half> ch;
#pragma unroll
            for (int i = 0; i < ch.num_elements; i++)
                ch.x[i] = __float2half_rn(c[et].x[i]);
            wmma::store_matrix_sync(out + (size_t)row0 * NF_C + h * HEAD_DIM_C + et * 16,
                                    ch, NF_C, wmma::mem_row_major);
        }
    }
}

// ---------------------------------------------------------------------------
// Bucket build
// ---------------------------------------------------------------------------
__global__ void zero_cnt_kernel() {
    int t = blockIdx.x * blockDim.x + threadIdx.x;
    if (t < N_NODES_C) g_cnt[t] = 0;
    if (t == 0) g_ovf_cnt = 0;
}

__global__ void bucket_kernel(const int* __restrict__ idx_i,
                              const int* __restrict__ idx_j) {
    int e = blockIdx.x * blockDim.x + threadIdx.x;
    if (e >= N_PAIRS_C) return;
    int i = idx_i[e];
    int pos = atomicAdd(&g_cnt[i], 1);
    if (pos < CAP) {
        g_bkt[(size_t)i * CAP + pos] = make_int2(e, idx_j[e]);
    } else {
        int p = atomicAdd(&g_ovf_cnt, 1);
        if (p < OVF_CAP) g_ovf[p] = e;
    }
}

// ---------------------------------------------------------------------------
// dot helper
// ---------------------------------------------------------------------------
__device__ __forceinline__ float dot8_h(uint4 qu, uint4 ku, float4 w0, float4 w1) {
    const __half2* q2 = (const __half2*)&qu;
    const __half2* k2 = (const __half2*)&ku;
    float2 qf0 = __half22float2(q2[0]);
    float2 qf1 = __half22float2(q2[1]);
    float2 qf2 = __half22float2(q2[2]);
    float2 qf3 = __half22float2(q2[3]);
    float2 kf0 = __half22float2(k2[0]);
    float2 kf1 = __half22float2(k2[1]);
    float2 kf2 = __half22float2(k2[2]);
    float2 kf3 = __half22float2(k2[3]);
    float s;
    s  = qf0.x * w0.x * kf0.x;
    s += qf0.y * w0.y * kf0.y;
    s += qf1.x * w0.z * kf1.x;
    s += qf1.y * w0.w * kf1.y;
    s += qf2.x * w1.x * kf2.x;
    s += qf2.y * w1.y * kf2.y;
    s += qf3.x * w1.z * kf3.x;
    s += qf3.y * w1.w * kf3.y;
    return s;
}

// ---------------------------------------------------------------------------
// Kernel A: alpha stream (2-edge unroll, measured-good version)
// ---------------------------------------------------------------------------
__global__ void __launch_bounds__(256)
alpha_kernel(const float* __restrict__ w_ij,
             const int* __restrict__ idx_i,
             const int* __restrict__ idx_j,
             const float* __restrict__ phi) {
    int warp = (blockIdx.x * blockDim.x + threadIdx.x) >> 5;
    int lane = threadIdx.x & 31;
    int e0 = warp * 2;
    if (e0 >= N_PAIRS_C) return;
    int e1 = e0 + 1;
    int off = lane * 8;

    int   i0 = __ldg(&idx_i[e0]), i1 = __ldg(&idx_i[e1]);
    int   j0 = __ldg(&idx_j[e0]), j1 = __ldg(&idx_j[e1]);
    float p0 = __ldg(&phi[e0]),   p1 = __ldg(&phi[e1]);

    const float4* wp0 = (const float4*)(w_ij + (size_t)e0 * NF_C + off);
    const float4* wp1 = (const float4*)(w_ij + (size_t)e1 * NF_C + off);
    float4 w00 = __ldcs(wp0);
    float4 w01 = __ldcs(wp0 + 1);
    float4 w10 = __ldcs(wp1);
    float4 w11 = __ldcs(wp1 + 1);

    uint4 qu0 = __ldg((const uint4*)(g_q + (size_t)i0 * NF_C + off));
    uint4 ku0 = __ldg((const uint4*)(g_k + (size_t)j0 * NF_C + off));
    uint4 qu1 = __ldg((const uint4*)(g_q + (size_t)i1 * NF_C + off));
    uint4 ku1 = __ldg((const uint4*)(g_k + (size_t)j1 * NF_C + off));

    float s0 = dot8_h(qu0, ku0, w00, w01);
    float s1 = dot8_h(qu1, ku1, w10, w11);

    s0 += __shfl_xor_sync(0xffffffffu, s0, 1);
    s1 += __shfl_xor_sync(0xffffffffu, s1, 1);
    s0 += __shfl_xor_sync(0xffffffffu, s0, 2);
    s1 += __shfl_xor_sync(0xffffffffu, s1, 2);
    s0 += __shfl_xor_sync(0xffffffffu, s0, 4);
    s1 += __shfl_xor_sync(0xffffffffu, s1, 4);

    if ((lane & 7) == 0) {
        int h = lane >> 3;
        g_alpha[(size_t)e0 * NHEADS_C + h] = s0 * 0.125f * p0;
        g_alpha[(size_t)e1 * NHEADS_C + h] = s1 * 0.125f * p1;
    }
}

// ---------------------------------------------------------------------------
// Kernel B: gather-accumulate (2-edge unroll, measured-good version)
// ---------------------------------------------------------------------------
__global__ void __launch_bounds__(256)
accum_kernel(float* __restrict__ y) {
    int node = (blockIdx.x * blockDim.x + threadIdx.x) >> 5;
    int lane = threadIdx.x & 31;
    if (node >= N_NODES_C) return;

    int deg = g_cnt[node];
    if (deg > CAP) deg = CAP;
    const size_t base = (size_t)node * CAP;
    const int off  = lane * 8;
    const int head = lane >> 3;

    float a0 = 0.f, a1 = 0.f, a2 = 0.f, a3 = 0.f;
    float a4 = 0.f, a5 = 0.f, a6 = 0.f, a7 = 0.f;

    int t = 0;
    for (; t + 2 <= deg; t += 2) {
        int2 m0 = g_bkt[base + t];
        int2 m1 = g_bkt[base + t + 1];
        float al0 = __ldg(&g_alpha[(size_t)m0.x * NHEADS_C + head]);
        float al1 = __ldg(&g_alpha[(size_t)m1.x * NHEADS_C + head]);
        uint4 vu0 = __ldg((const uint4*)(g_v + (size_t)m0.y * NF_C + off));
        uint4 vu1 = __ldg((const uint4*)(g_v + (size_t)m1.y * NF_C + off));

        const __half2* v20 = (const __half2*)&vu0;
        const __half2* v21 = (const __half2*)&vu1;
        float2 f;
        f = __half22float2(v20[0]); a0 = fmaf(al0, f.x, a0); a1 = fmaf(al0, f.y, a1);
        f = __half22float2(v20[1]); a2 = fmaf(al0, f.x, a2); a3 = fmaf(al0, f.y, a3);
        f = __half22float2(v20[2]); a4 = fmaf(al0, f.x, a4); a5 = fmaf(al0, f.y, a5);
        f = __half22float2(v20[3]); a6 = fmaf(al0, f.x, a6); a7 = fmaf(al0, f.y, a7);
        f = __half22float2(v21[0]); a0 = fmaf(al1, f.x, a0); a1 = fmaf(al1, f.y, a1);
        f = __half22float2(v21[1]); a2 = fmaf(al1, f.x, a2); a3 = fmaf(al1, f.y, a3);
        f = __half22float2(v21[2]); a4 = fmaf(al1, f.x, a4); a5 = fmaf(al1, f.y, a5);
        f = __half22float2(v21[3]); a6 = fmaf(al1, f.x, a6); a7 = fmaf(al1, f.y, a7);
    }
    if (t < deg) {
        int2 m0 = g_bkt[base + t];
        float al0 = __ldg(&g_alpha[(size_t)m0.x * NHEADS_C + head]);
        uint4 vu0 = __ldg((const uint4*)(g_v + (size_t)m0.y * NF_C + off));
        const __half2* v20 = (const __half2*)&vu0;
        float2 f;
        f = __half22float2(v20[0]); a0 = fmaf(al0, f.x, a0); a1 = fmaf(al0, f.y, a1);
        f = __half22float2(v20[1]); a2 = fmaf(al0, f.x, a2); a3 = fmaf(al0, f.y, a3);
        f = __half22float2(v20[2]); a4 = fmaf(al0, f.x, a4); a5 = fmaf(al0, f.y, a5);
        f = __half22float2(v20[3]); a6 = fmaf(al0, f.x, a6); a7 = fmaf(al0, f.y, a7);
    }

    float4* yp = (float4*)(y + (size_t)node * NF_C + off);
    yp[0] = make_float4(a0, a1, a2, a3);
    yp[1] = make_float4(a4, a5, a6, a7);
}

// ---------------------------------------------------------------------------
// Overflow fallback
// ---------------------------------------------------------------------------
__global__ void overflow_kernel(const int* __restrict__ idx_i,
                                const int* __restrict__ idx_j,
                                float* __restrict__ y) {
    int n = g_ovf_cnt;
    if (n > OVF_CAP) n = OVF_CAP;
    int lane = threadIdx.x & 31;
    for (int t = (int)(threadIdx.x >> 5); t < n; t += (int)(blockDim.x >> 5)) {
        int e = g_ovf[t];
        int i = idx_i[e];
        int j = idx_j[e];
        int off = lane * 8;
        int head = lane >> 3;

        float alpha = g_alpha[(size_t)e * NHEADS_C + head];
        uint4 vu = *(const uint4*)(g_v + (size_t)j * NF_C + off);
        const __half2* v2 = (const __half2*)&vu;
        float2 f0 = __half22float2(v2[0]);
        float2 f1 = __half22float2(v2[1]);
        float2 f2 = __half22float2(v2[2]);
        float2 f3 = __half22float2(v2[3]);
        float* yp = y + (size_t)i * NF_C + off;
        atomicAdd(yp + 0, alpha * f0.x);
        atomicAdd(yp + 1, alpha * f0.y);
        atomicAdd(yp + 2, alpha * f1.x);
        atomicAdd(yp + 3, alpha * f1.y);
        atomicAdd(yp + 4, alpha * f2.x);
        atomicAdd(yp + 5, alpha * f2.y);
        atomicAdd(yp + 6, alpha * f3.x);
        atomicAdd(yp + 7, alpha * f3.y);
    }
}

// ---------------------------------------------------------------------------
// launch
// ---------------------------------------------------------------------------
extern "C" void kernel_launch(void* const* d_in, const int* in_sizes, int n_in,
                              void* d_out, int out_size) {
    const float* x     = (const float*)d_in[0];
    const float* w_ij  = (const float*)d_in[1];
    const int*   idx_i = (const int*)d_in[2];
    const int*   idx_j = (const int*)d_in[3];
    const float* phi   = (const float*)d_in[4];
    const float* Wq    = (const float*)d_in[5];
    const float* Wk    = (const float*)d_in[6];
    const float* Wv    = (const float*)d_in[7];
    float* y = (float*)d_out;

    // fp16 weight conversion
    conv_w_kernel<<<48, 256>>>(Wq, Wk, Wv);

    // bucket build
    zero_cnt_kernel<<<(N_NODES_C + 255) / 256, 256>>>();
    bucket_kernel<<<(N_PAIRS_C + 255) / 256, 256>>>(idx_i, idx_j);

    // tensor-core projection (512 threads, 128 rows, 2 blocks/SM)
    cudaFuncSetAttribute(proj_wmma_kernel,
                         cudaFuncAttributeMaxDynamicSharedMemorySize,
                         PROJ_SMEM_BYTES);
    dim3 pgrid((N_NODES_C + PB_ROWS - 1) / PB_ROWS, 3);   // (391, 3)
    proj_wmma_kernel<<<pgrid, PROJ_THREADS, PROJ_SMEM_BYTES>>>(x);

    // A: alpha stream (2 edges per warp)
    int ablocks = (N_PAIRS_C + 15) / 16;
    alpha_kernel<<<ablocks, 256>>>(w_ij, idx_i, idx_j, phi);

    // B: gather-accumulate
    int nblocks = (N_NODES_C + 7) / 8;
    accum_kernel<<<nblocks, 256>>>(y);

    // overflow (usually empty)
    overflow_kernel<<<1, 256>>>(idx_i, idx_j, y);
}